// round 1
// baseline (speedup 1.0000x reference)
#include <cuda_runtime.h>
#include <cstdint>

// Problem constants (fixed by the dataset)
#define NMAX   100000
#define DN     64
#define NGR    128

// ---------------- device scratch (allocation-free) ----------------
__device__ float g_buf0[NMAX * DN];   // scaled features / layer outputs
__device__ float g_buf1[NMAX * DN];   // aggregation target
__device__ int   g_deg[2 * NMAX];     // [0,N): out-degree(src), [N,2N): in-degree(dst)
__device__ float g_norm[2 * NMAX];    // [0,N): norm_src, [N,2N): norm_dst
__device__ float g_pooled[NGR * DN];
__device__ float g_counts[NGR];

// ---------------- zero kernels ----------------
__global__ void k_zero_deg(int n2) {
    int i = blockIdx.x * blockDim.x + threadIdx.x;
    if (i < n2) g_deg[i] = 0;
}
__global__ void k_zero_buf1(int n4) {  // n4 = N*16 float4s
    int i = blockIdx.x * blockDim.x + threadIdx.x;
    if (i < n4) reinterpret_cast<float4*>(g_buf1)[i] = make_float4(0.f, 0.f, 0.f, 0.f);
}
__global__ void k_zero_pool() {
    int i = blockIdx.x * blockDim.x + threadIdx.x;
    if (i < NGR * DN) g_pooled[i] = 0.f;
    if (i < NGR)      g_counts[i] = 0.f;
}

// ---------------- degrees + norms ----------------
__global__ void k_degree(const int* __restrict__ src, const int* __restrict__ dst, int E, int N) {
    int e = blockIdx.x * blockDim.x + threadIdx.x;
    if (e < E) {
        atomicAdd(&g_deg[src[e]], 1);
        atomicAdd(&g_deg[N + dst[e]], 1);
    }
}
__global__ void k_norm(int N) {
    int n = blockIdx.x * blockDim.x + threadIdx.x;
    if (n < N) {
        g_norm[n]     = rsqrtf((float)max(g_deg[n], 1));
        g_norm[N + n] = rsqrtf((float)max(g_deg[N + n], 1));
    }
}

// xs = h * norm_src  -> g_buf0
__global__ void k_scale_src(const float4* __restrict__ h, int N) {
    int t = blockIdx.x * blockDim.x + threadIdx.x;
    if (t < N * 16) {
        int n = t >> 4;
        float s = g_norm[n];
        float4 v = h[t];
        v.x *= s; v.y *= s; v.z *= s; v.w *= s;
        reinterpret_cast<float4*>(g_buf0)[t] = v;
    }
}

// ---------------- edge scatter: agg[dst] += xs[src] ----------------
// thread t: edge e = t/16, float4 chunk c = t%16. Reads g_buf0, reduces into g_buf1.
__global__ void k_scatter(const int* __restrict__ src, const int* __restrict__ dst, int E) {
    int t = blockIdx.x * blockDim.x + threadIdx.x;
    if (t >= E * 16) return;
    int e = t >> 4;
    int c = t & 15;
    int s = __ldg(&src[e]);
    int d = __ldg(&dst[e]);
    float4 v = reinterpret_cast<const float4*>(g_buf0)[(size_t)s * 16 + c];
    float* p = g_buf1 + ((size_t)d * DN + c * 4);
    asm volatile("red.global.add.v4.f32 [%0], {%1,%2,%3,%4};"
                 :: "l"(p), "f"(v.x), "f"(v.y), "f"(v.z), "f"(v.w)
                 : "memory");
}

// ---------------- GEMM: out = relu(norm_dst[n]*(agg[n] @ W) + b) [* norm_src[n]] ----------------
// Block: 256 threads handle 128 nodes; thread = (node, half), 32 output columns each.
template<bool SCALE_SRC>
__global__ void __launch_bounds__(256) k_gemm(const float* __restrict__ W,
                                              const float* __restrict__ b, int N) {
    __shared__ float Ws[DN * DN];       // 16 KB, row-major [k][j]
    int tid = threadIdx.x;
    #pragma unroll
    for (int i = tid; i < DN * DN; i += 256) Ws[i] = W[i];
    __syncthreads();

    int local = tid >> 1;               // node within block
    int half  = tid & 1;                // column half: 0 -> cols 0..31, 1 -> 32..63
    int n = blockIdx.x * 128 + local;
    if (n >= N) return;

    const float4* arow = reinterpret_cast<const float4*>(g_buf1 + (size_t)n * DN);
    const float4* WsV  = reinterpret_cast<const float4*>(Ws);
    int qb = half * 8;                  // float4 column offset within a W row

    float acc[32];
    #pragma unroll
    for (int j = 0; j < 32; j++) acc[j] = 0.f;

    #pragma unroll
    for (int kk = 0; kk < 16; kk++) {
        float4 a = arow[kk];
        #pragma unroll
        for (int r = 0; r < 4; r++) {
            int k = kk * 4 + r;
            float av = (r == 0) ? a.x : (r == 1) ? a.y : (r == 2) ? a.z : a.w;
            #pragma unroll
            for (int q = 0; q < 8; q++) {
                float4 w = WsV[k * 16 + qb + q];
                acc[q * 4 + 0] += av * w.x;
                acc[q * 4 + 1] += av * w.y;
                acc[q * 4 + 2] += av * w.z;
                acc[q * 4 + 3] += av * w.w;
            }
        }
    }

    float nd = g_norm[N + n];
    float ns = SCALE_SRC ? g_norm[n] : 1.f;
    float* orow = g_buf0 + (size_t)n * DN + half * 32;
    #pragma unroll
    for (int j = 0; j < 32; j++) {
        float v = fmaxf(acc[j] * nd + __ldg(&b[half * 32 + j]), 0.f);
        orow[j] = v * ns;
    }
}

// ---------------- per-graph mean pool (graph_ids sorted -> run-length accumulate) ----------------
#define POOL_CHUNK 128
__global__ void k_pool(const int* __restrict__ gid, int N) {
    int c = threadIdx.x;                // 64 threads = feature columns
    int n0 = blockIdx.x * POOL_CHUNK;
    if (n0 >= N) return;
    int n1 = min(n0 + POOL_CHUNK, N);

    float acc = 0.f, cnt = 0.f;
    int cur = __ldg(&gid[n0]);
    for (int n = n0; n < n1; n++) {
        int g = __ldg(&gid[n]);
        if (g != cur) {
            atomicAdd(&g_pooled[cur * DN + c], acc);
            if (c == 0) atomicAdd(&g_counts[cur], cnt);
            acc = 0.f; cnt = 0.f; cur = g;
        }
        acc += g_buf0[(size_t)n * DN + c];
        cnt += 1.f;
    }
    atomicAdd(&g_pooled[cur * DN + c], acc);
    if (c == 0) atomicAdd(&g_counts[cur], cnt);
}

// ---------------- classifier: out[g,k] = (pooled[g]/count[g]) @ Wc + bc ----------------
__global__ void k_classify(const float* __restrict__ Wc, const float* __restrict__ bc,
                           float* __restrict__ out) {
    int g = blockIdx.x;
    int k = threadIdx.x;
    __shared__ float row[DN];
    if (k < DN) row[k] = g_pooled[g * DN + k];
    __syncthreads();
    if (k < 10) {
        float sum = 0.f;
        #pragma unroll
        for (int i = 0; i < DN; i++) sum += row[i] * __ldg(&Wc[i * 10 + k]);
        out[g * 10 + k] = sum / fmaxf(g_counts[g], 1.f) + __ldg(&bc[k]);
    }
}

// ---------------- launch ----------------
extern "C" void kernel_launch(void* const* d_in, const int* in_sizes, int n_in,
                              void* d_out, int out_size) {
    const float* h  = (const float*)d_in[0];
    const float* W1 = (const float*)d_in[1];
    const float* b1 = (const float*)d_in[2];
    const float* W2 = (const float*)d_in[3];
    const float* b2 = (const float*)d_in[4];
    const float* Wc = (const float*)d_in[5];
    const float* bc = (const float*)d_in[6];
    const int* src  = (const int*)d_in[7];
    const int* dst  = (const int*)d_in[8];
    const int* gid  = (const int*)d_in[9];
    float* out = (float*)d_out;

    const int N = in_sizes[9];          // 100000
    const int E = in_sizes[7];          // 1600000
    const int TPB = 256;

    // degrees + norms
    k_zero_deg<<<(2 * N + TPB - 1) / TPB, TPB>>>(2 * N);
    k_degree<<<(E + TPB - 1) / TPB, TPB>>>(src, dst, E, N);
    k_norm<<<(N + TPB - 1) / TPB, TPB>>>(N);

    // layer 1
    k_scale_src<<<(N * 16 + TPB - 1) / TPB, TPB>>>((const float4*)h, N);
    k_zero_buf1<<<(N * 16 + TPB - 1) / TPB, TPB>>>(N * 16);
    k_scatter<<<((long long)E * 16 + TPB - 1) / TPB, TPB>>>(src, dst, E);
    k_gemm<true><<<(N + 127) / 128, 256>>>(W1, b1, N);   // h1*norm_src -> g_buf0

    // layer 2
    k_zero_buf1<<<(N * 16 + TPB - 1) / TPB, TPB>>>(N * 16);
    k_scatter<<<((long long)E * 16 + TPB - 1) / TPB, TPB>>>(src, dst, E);
    k_gemm<false><<<(N + 127) / 128, 256>>>(W2, b2, N);  // h2 -> g_buf0

    // pool + classify
    k_zero_pool<<<(NGR * DN + TPB - 1) / TPB, TPB>>>();
    k_pool<<<(N + POOL_CHUNK - 1) / POOL_CHUNK, DN>>>(gid, N);
    k_classify<<<NGR, DN>>>(Wc, bc, out);
}

// round 2
// speedup vs baseline: 1.6017x; 1.6017x over previous
#include <cuda_runtime.h>
#include <cstdint>

#define NMAX 100000
#define EMAX 1600000
#define DN   64
#define NGR  128

// ---------------- device scratch (allocation-free) ----------------
__device__ float g_bufA[NMAX * DN];    // layer outputs (gemm out, pool in)
__device__ float g_bufB[NMAX * DN];    // aggregation target (gather out, gemm in)
__device__ int   g_deg[2 * NMAX];      // [0,N): out-deg(src), [N,2N): in-deg(dst)
__device__ float g_norm[2 * NMAX];     // [0,N): norm_src, [N,2N): norm_dst
__device__ int   g_off[NMAX];          // CSR row offsets (by dst)
__device__ int   g_blk[1024];          // scan block totals
__device__ int   g_cursor[NMAX];       // CSR fill cursors
__device__ int   g_csr[EMAX];          // CSR: src indices grouped by dst
__device__ float g_pooled[NGR * DN];
__device__ float g_counts[NGR];

// ---------------- init: zero everything that gets accumulated ----------------
__global__ void k_zero_init(int N) {
    int i = blockIdx.x * blockDim.x + threadIdx.x;
    if (i < 2 * N)      g_deg[i] = 0;
    if (i < N)          g_cursor[i] = 0;
    if (i < NGR * DN)   g_pooled[i] = 0.f;
    if (i < NGR)        g_counts[i] = 0.f;
}

// ---------------- degrees ----------------
__global__ void k_degree(const int* __restrict__ src, const int* __restrict__ dst, int E, int N) {
    int e = blockIdx.x * blockDim.x + threadIdx.x;
    if (e < E) {
        atomicAdd(&g_deg[src[e]], 1);
        atomicAdd(&g_deg[N + dst[e]], 1);
    }
}

__global__ void k_norm(int N) {
    int n = blockIdx.x * blockDim.x + threadIdx.x;
    if (n < N) {
        g_norm[n]     = rsqrtf((float)max(g_deg[n], 1));
        g_norm[N + n] = rsqrtf((float)max(g_deg[N + n], 1));
    }
}

// ---------------- exclusive scan of in-degree -> g_off ----------------
__global__ void k_scanA(int N) {           // grid = ceil(N/1024), block = 1024
    __shared__ int sh[1024];
    int b = blockIdx.x, t = threadIdx.x, i = b * 1024 + t;
    int v = (i < N) ? g_deg[NMAX ? (N + i) : 0] : 0;  // in-degree
    sh[t] = v;
    __syncthreads();
    #pragma unroll
    for (int o = 1; o < 1024; o <<= 1) {
        int x = (t >= o) ? sh[t - o] : 0;
        __syncthreads();
        sh[t] += x;
        __syncthreads();
    }
    if (i < N) g_off[i] = sh[t] - v;       // exclusive
    if (t == 1023) g_blk[b] = sh[1023];
}
__global__ void k_scanB(int G) {
    if (threadIdx.x == 0) {
        int s = 0;
        for (int b = 0; b < G; b++) { int v = g_blk[b]; g_blk[b] = s; s += v; }
    }
}
__global__ void k_scanC(int N) {
    int i = blockIdx.x * blockDim.x + threadIdx.x;
    if (i < N) g_off[i] += g_blk[i >> 10];
}

// ---------------- fill CSR (src grouped by dst) ----------------
__global__ void k_fill(const int* __restrict__ src, const int* __restrict__ dst, int E) {
    int e = blockIdx.x * blockDim.x + threadIdx.x;
    if (e < E) {
        int d = dst[e];
        int p = atomicAdd(&g_cursor[d], 1);
        g_csr[g_off[d] + p] = src[e];
    }
}

// ---------------- gather-sum per dst node: agg[n] = norm_dst[n] * sum xs[src] ----------------
// 16 threads per node, float4 per thread. FIRST: read h * norm_src; else read g_bufA.
template<bool FIRST>
__global__ void __launch_bounds__(256) k_gather(const float4* __restrict__ h, int N) {
    int tid = blockIdx.x * blockDim.x + threadIdx.x;
    int node = tid >> 4;
    if (node >= N) return;
    int q = tid & 15;

    int o = g_off[node];
    int d = g_deg[N + node];
    const float4* X = FIRST ? h : reinterpret_cast<const float4*>(g_bufA);

    float4 acc = make_float4(0.f, 0.f, 0.f, 0.f);
    int s_next = (d > 0) ? __ldg(&g_csr[o]) : 0;
    for (int j = 0; j < d; j++) {
        int s = s_next;
        if (j + 1 < d) s_next = __ldg(&g_csr[o + j + 1]);
        float4 v = __ldg(&X[(size_t)s * 16 + q]);
        if (FIRST) {
            float sc = __ldg(&g_norm[s]);
            acc.x += v.x * sc; acc.y += v.y * sc; acc.z += v.z * sc; acc.w += v.w * sc;
        } else {
            acc.x += v.x; acc.y += v.y; acc.z += v.z; acc.w += v.w;
        }
    }
    float nd = g_norm[N + node];
    acc.x *= nd; acc.y *= nd; acc.z *= nd; acc.w *= nd;
    reinterpret_cast<float4*>(g_bufB)[(size_t)node * 16 + q] = acc;
}

// ---------------- GEMM: g_bufA[n] = relu(g_bufB[n] @ W + b) [* norm_src[n]] ----------------
// 256 threads / block, 2 nodes per thread (n0, n0+128), 32 cols each -> Ws reuse 2B/FMA.
template<bool SCALE_SRC>
__global__ void __launch_bounds__(256) k_gemm(const float* __restrict__ W,
                                              const float* __restrict__ b, int N) {
    __shared__ float Ws[DN * DN];
    __shared__ float bs[DN];
    int tid = threadIdx.x;
    for (int i = tid; i < DN * DN; i += 256) Ws[i] = W[i];
    if (tid < DN) bs[tid] = b[tid];
    __syncthreads();

    int idx = tid >> 1, half = tid & 1;
    int n0 = blockIdx.x * 256 + idx;
    int n1 = n0 + 128;
    bool v0 = n0 < N, v1 = n1 < N;

    const float4* WsV = reinterpret_cast<const float4*>(Ws);
    const float4* a0 = reinterpret_cast<const float4*>(g_bufB + (size_t)n0 * DN);
    const float4* a1 = reinterpret_cast<const float4*>(g_bufB + (size_t)n1 * DN);
    int qb = half * 8;

    float acc0[32], acc1[32];
    #pragma unroll
    for (int j = 0; j < 32; j++) { acc0[j] = 0.f; acc1[j] = 0.f; }

    #pragma unroll
    for (int kk = 0; kk < 16; kk++) {
        float4 A0 = v0 ? a0[kk] : make_float4(0.f, 0.f, 0.f, 0.f);
        float4 A1 = v1 ? a1[kk] : make_float4(0.f, 0.f, 0.f, 0.f);
        #pragma unroll
        for (int r = 0; r < 4; r++) {
            int k = kk * 4 + r;
            float x0 = (r == 0) ? A0.x : (r == 1) ? A0.y : (r == 2) ? A0.z : A0.w;
            float x1 = (r == 0) ? A1.x : (r == 1) ? A1.y : (r == 2) ? A1.z : A1.w;
            #pragma unroll
            for (int q = 0; q < 8; q++) {
                float4 w = WsV[k * 16 + qb + q];
                acc0[q * 4 + 0] += x0 * w.x; acc0[q * 4 + 1] += x0 * w.y;
                acc0[q * 4 + 2] += x0 * w.z; acc0[q * 4 + 3] += x0 * w.w;
                acc1[q * 4 + 0] += x1 * w.x; acc1[q * 4 + 1] += x1 * w.y;
                acc1[q * 4 + 2] += x1 * w.z; acc1[q * 4 + 3] += x1 * w.w;
            }
        }
    }

    if (v0) {
        float ns = SCALE_SRC ? g_norm[n0] : 1.f;
        float4* o4 = reinterpret_cast<float4*>(g_bufA + (size_t)n0 * DN + half * 32);
        #pragma unroll
        for (int q = 0; q < 8; q++) {
            o4[q] = make_float4(
                fmaxf(acc0[q * 4 + 0] + bs[half * 32 + q * 4 + 0], 0.f) * ns,
                fmaxf(acc0[q * 4 + 1] + bs[half * 32 + q * 4 + 1], 0.f) * ns,
                fmaxf(acc0[q * 4 + 2] + bs[half * 32 + q * 4 + 2], 0.f) * ns,
                fmaxf(acc0[q * 4 + 3] + bs[half * 32 + q * 4 + 3], 0.f) * ns);
        }
    }
    if (v1) {
        float ns = SCALE_SRC ? g_norm[n1] : 1.f;
        float4* o4 = reinterpret_cast<float4*>(g_bufA + (size_t)n1 * DN + half * 32);
        #pragma unroll
        for (int q = 0; q < 8; q++) {
            o4[q] = make_float4(
                fmaxf(acc1[q * 4 + 0] + bs[half * 32 + q * 4 + 0], 0.f) * ns,
                fmaxf(acc1[q * 4 + 1] + bs[half * 32 + q * 4 + 1], 0.f) * ns,
                fmaxf(acc1[q * 4 + 2] + bs[half * 32 + q * 4 + 2], 0.f) * ns,
                fmaxf(acc1[q * 4 + 3] + bs[half * 32 + q * 4 + 3], 0.f) * ns);
        }
    }
}

// ---------------- per-graph mean pool (graph_ids sorted -> run-length accumulate) ----------------
#define POOL_CHUNK 64
__global__ void k_pool(const int* __restrict__ gid, int N) {
    int c = threadIdx.x;                // 64 threads = feature columns
    int n0 = blockIdx.x * POOL_CHUNK;
    if (n0 >= N) return;
    int n1 = min(n0 + POOL_CHUNK, N);

    float acc = 0.f, cnt = 0.f;
    int cur = __ldg(&gid[n0]);
    for (int n = n0; n < n1; n++) {
        int g = __ldg(&gid[n]);
        if (g != cur) {
            atomicAdd(&g_pooled[cur * DN + c], acc);
            if (c == 0) atomicAdd(&g_counts[cur], cnt);
            acc = 0.f; cnt = 0.f; cur = g;
        }
        acc += g_bufA[(size_t)n * DN + c];
        cnt += 1.f;
    }
    atomicAdd(&g_pooled[cur * DN + c], acc);
    if (c == 0) atomicAdd(&g_counts[cur], cnt);
}

// ---------------- classifier ----------------
__global__ void k_classify(const float* __restrict__ Wc, const float* __restrict__ bc,
                           float* __restrict__ out) {
    int g = blockIdx.x;
    int k = threadIdx.x;
    __shared__ float row[DN];
    if (k < DN) row[k] = g_pooled[g * DN + k];
    __syncthreads();
    if (k < 10) {
        float sum = 0.f;
        #pragma unroll
        for (int i = 0; i < DN; i++) sum += row[i] * __ldg(&Wc[i * 10 + k]);
        out[g * 10 + k] = sum / fmaxf(g_counts[g], 1.f) + __ldg(&bc[k]);
    }
}

// ---------------- launch ----------------
extern "C" void kernel_launch(void* const* d_in, const int* in_sizes, int n_in,
                              void* d_out, int out_size) {
    const float* h  = (const float*)d_in[0];
    const float* W1 = (const float*)d_in[1];
    const float* b1 = (const float*)d_in[2];
    const float* W2 = (const float*)d_in[3];
    const float* b2 = (const float*)d_in[4];
    const float* Wc = (const float*)d_in[5];
    const float* bc = (const float*)d_in[6];
    const int* src  = (const int*)d_in[7];
    const int* dst  = (const int*)d_in[8];
    const int* gid  = (const int*)d_in[9];
    float* out = (float*)d_out;

    const int N = in_sizes[9];          // 100000
    const int E = in_sizes[7];          // 1600000
    const int TPB = 256;
    const int G = (N + 1023) / 1024;

    // ---- CSR build (once per launch) ----
    k_zero_init<<<(2 * N + TPB - 1) / TPB, TPB>>>(N);
    k_degree<<<(E + TPB - 1) / TPB, TPB>>>(src, dst, E, N);
    k_scanA<<<G, 1024>>>(N);
    k_scanB<<<1, 32>>>(G);
    k_scanC<<<(N + TPB - 1) / TPB, TPB>>>(N);
    k_norm<<<(N + TPB - 1) / TPB, TPB>>>(N);
    k_fill<<<(E + TPB - 1) / TPB, TPB>>>(src, dst, E);

    // ---- layer 1: gather (h * norm_src) -> bufB; gemm -> bufA (carries *norm_src) ----
    k_gather<true><<<(N * 16 + TPB - 1) / TPB, TPB>>>((const float4*)h, N);
    k_gemm<true><<<(N + 255) / 256, 256>>>(W1, b1, N);

    // ---- layer 2: gather (bufA) -> bufB; gemm -> bufA ----
    k_gather<false><<<(N * 16 + TPB - 1) / TPB, TPB>>>(nullptr, N);
    k_gemm<false><<<(N + 255) / 256, 256>>>(W2, b2, N);

    // ---- pool + classify ----
    k_pool<<<(N + POOL_CHUNK - 1) / POOL_CHUNK, DN>>>(gid, N);
    k_classify<<<NGR, DN>>>(Wc, bc, out);
}

// round 3
// speedup vs baseline: 1.6863x; 1.0528x over previous
#include <cuda_runtime.h>
#include <cstdint>

#define NMAX 100000
#define EMAX 1600000
#define DN   64
#define NGR  128

// ---------------- device scratch (allocation-free) ----------------
__device__ float g_bufA[NMAX * DN];    // layer outputs (gemm out, pool in)
__device__ float g_bufB[NMAX * DN];    // aggregation target (gather out, gemm in)
__device__ int   g_deg[2 * NMAX];      // [0,N): out-deg(src), [N,2N): in-deg(dst)
__device__ float g_norm[2 * NMAX];     // [0,N): norm_src, [N,2N): norm_dst
__device__ int   g_off[NMAX];          // CSR row offsets (by dst) — immutable after scan
__device__ int   g_blk[128];           // scan block totals
__device__ int   g_cursor[NMAX];       // CSR fill cursors (seeded = g_off)
__device__ int   g_csr[EMAX];          // CSR: src indices grouped by dst
__device__ float g_pooled[NGR * DN];
__device__ float g_counts[NGR];

// ---------------- init: zero accumulated arrays ----------------
__global__ void k_zero_init(int N) {
    int i = blockIdx.x * blockDim.x + threadIdx.x;
    if (i < 2 * N)      g_deg[i] = 0;
    if (i < NGR * DN)   g_pooled[i] = 0.f;
    if (i < NGR)        g_counts[i] = 0.f;
}

// ---------------- degrees ----------------
__global__ void k_degree(const int* __restrict__ src, const int* __restrict__ dst, int E, int N) {
    int e = blockIdx.x * blockDim.x + threadIdx.x;
    if (e < E) {
        atomicAdd(&g_deg[src[e]], 1);
        atomicAdd(&g_deg[N + dst[e]], 1);
    }
}

// ---------------- exclusive scan of in-degree -> g_off ----------------
__global__ void k_scanA(int N) {           // grid = ceil(N/1024), block = 1024
    __shared__ int sh[1024];
    int b = blockIdx.x, t = threadIdx.x, i = b * 1024 + t;
    int v = (i < N) ? g_deg[N + i] : 0;    // in-degree
    sh[t] = v;
    __syncthreads();
    #pragma unroll
    for (int o = 1; o < 1024; o <<= 1) {
        int x = (t >= o) ? sh[t - o] : 0;
        __syncthreads();
        sh[t] += x;
        __syncthreads();
    }
    if (i < N) g_off[i] = sh[t] - v;       // exclusive within block
    if (t == 1023) g_blk[b] = sh[1023];
}
// parallel scan of block totals (G <= 128)
__global__ void k_scanB(int G) {
    __shared__ int sh[128];
    int t = threadIdx.x;
    int v = (t < G) ? g_blk[t] : 0;
    sh[t] = v;
    __syncthreads();
    #pragma unroll
    for (int o = 1; o < 128; o <<= 1) {
        int x = (t >= o) ? sh[t - o] : 0;
        __syncthreads();
        sh[t] += x;
        __syncthreads();
    }
    if (t < G) g_blk[t] = sh[t] - v;       // exclusive
}
// finalize offsets, seed cursors, compute norms — fused
__global__ void k_scanC_norm(int N) {
    int i = blockIdx.x * blockDim.x + threadIdx.x;
    if (i < N) {
        int o = g_off[i] + g_blk[i >> 10];
        g_off[i] = o;
        g_cursor[i] = o;
        g_norm[i]     = rsqrtf((float)max(g_deg[i], 1));
        g_norm[N + i] = rsqrtf((float)max(g_deg[N + i], 1));
    }
}

// ---------------- fill CSR (src grouped by dst) ----------------
__global__ void k_fill(const int* __restrict__ src, const int* __restrict__ dst, int E) {
    int e = blockIdx.x * blockDim.x + threadIdx.x;
    if (e < E) {
        int p = atomicAdd(&g_cursor[dst[e]], 1);
        g_csr[p] = src[e];
    }
}

// ---------------- gather-sum per dst node ----------------
// 16 threads per node, float4 per thread. Unrolled x4 for MLP.
template<bool FIRST>
__global__ void __launch_bounds__(256) k_gather(const float4* __restrict__ h, int N) {
    int tid = blockIdx.x * blockDim.x + threadIdx.x;
    int node = tid >> 4;
    if (node >= N) return;
    int q = tid & 15;

    int o = g_off[node];
    int d = g_deg[N + node];
    const float4* X = FIRST ? h : reinterpret_cast<const float4*>(g_bufA);

    float4 a0 = make_float4(0.f, 0.f, 0.f, 0.f);
    float4 a1 = make_float4(0.f, 0.f, 0.f, 0.f);
    int j = 0;
    for (; j + 4 <= d; j += 4) {
        int s0 = __ldg(&g_csr[o + j]);
        int s1 = __ldg(&g_csr[o + j + 1]);
        int s2 = __ldg(&g_csr[o + j + 2]);
        int s3 = __ldg(&g_csr[o + j + 3]);
        float4 v0 = __ldg(&X[(size_t)s0 * 16 + q]);
        float4 v1 = __ldg(&X[(size_t)s1 * 16 + q]);
        float4 v2 = __ldg(&X[(size_t)s2 * 16 + q]);
        float4 v3 = __ldg(&X[(size_t)s3 * 16 + q]);
        if (FIRST) {
            float c0 = __ldg(&g_norm[s0]);
            float c1 = __ldg(&g_norm[s1]);
            float c2 = __ldg(&g_norm[s2]);
            float c3 = __ldg(&g_norm[s3]);
            a0.x = fmaf(v0.x, c0, a0.x); a0.y = fmaf(v0.y, c0, a0.y);
            a0.z = fmaf(v0.z, c0, a0.z); a0.w = fmaf(v0.w, c0, a0.w);
            a1.x = fmaf(v1.x, c1, a1.x); a1.y = fmaf(v1.y, c1, a1.y);
            a1.z = fmaf(v1.z, c1, a1.z); a1.w = fmaf(v1.w, c1, a1.w);
            a0.x = fmaf(v2.x, c2, a0.x); a0.y = fmaf(v2.y, c2, a0.y);
            a0.z = fmaf(v2.z, c2, a0.z); a0.w = fmaf(v2.w, c2, a0.w);
            a1.x = fmaf(v3.x, c3, a1.x); a1.y = fmaf(v3.y, c3, a1.y);
            a1.z = fmaf(v3.z, c3, a1.z); a1.w = fmaf(v3.w, c3, a1.w);
        } else {
            a0.x += v0.x; a0.y += v0.y; a0.z += v0.z; a0.w += v0.w;
            a1.x += v1.x; a1.y += v1.y; a1.z += v1.z; a1.w += v1.w;
            a0.x += v2.x; a0.y += v2.y; a0.z += v2.z; a0.w += v2.w;
            a1.x += v3.x; a1.y += v3.y; a1.z += v3.z; a1.w += v3.w;
        }
    }
    for (; j < d; j++) {
        int s = __ldg(&g_csr[o + j]);
        float4 v = __ldg(&X[(size_t)s * 16 + q]);
        if (FIRST) {
            float c = __ldg(&g_norm[s]);
            a0.x = fmaf(v.x, c, a0.x); a0.y = fmaf(v.y, c, a0.y);
            a0.z = fmaf(v.z, c, a0.z); a0.w = fmaf(v.w, c, a0.w);
        } else {
            a0.x += v.x; a0.y += v.y; a0.z += v.z; a0.w += v.w;
        }
    }
    float nd = g_norm[N + node];
    float4 acc = make_float4((a0.x + a1.x) * nd, (a0.y + a1.y) * nd,
                             (a0.z + a1.z) * nd, (a0.w + a1.w) * nd);
    reinterpret_cast<float4*>(g_bufB)[(size_t)node * 16 + q] = acc;
}

// ---------------- GEMM: g_bufA[n] = relu(g_bufB[n] @ W + b) [* norm_src[n]] ----------------
template<bool SCALE_SRC>
__global__ void __launch_bounds__(256) k_gemm(const float* __restrict__ W,
                                              const float* __restrict__ b, int N) {
    __shared__ float Ws[DN * DN];
    __shared__ float bs[DN];
    int tid = threadIdx.x;
    for (int i = tid; i < DN * DN; i += 256) Ws[i] = W[i];
    if (tid < DN) bs[tid] = b[tid];
    __syncthreads();

    int idx = tid >> 1, half = tid & 1;
    int n0 = blockIdx.x * 256 + idx;
    int n1 = n0 + 128;
    bool v0 = n0 < N, v1 = n1 < N;

    const float4* WsV = reinterpret_cast<const float4*>(Ws);
    const float4* a0 = reinterpret_cast<const float4*>(g_bufB + (size_t)n0 * DN);
    const float4* a1 = reinterpret_cast<const float4*>(g_bufB + (size_t)n1 * DN);
    int qb = half * 8;

    float acc0[32], acc1[32];
    #pragma unroll
    for (int j = 0; j < 32; j++) { acc0[j] = 0.f; acc1[j] = 0.f; }

    #pragma unroll
    for (int kk = 0; kk < 16; kk++) {
        float4 A0 = v0 ? a0[kk] : make_float4(0.f, 0.f, 0.f, 0.f);
        float4 A1 = v1 ? a1[kk] : make_float4(0.f, 0.f, 0.f, 0.f);
        #pragma unroll
        for (int r = 0; r < 4; r++) {
            int k = kk * 4 + r;
            float x0 = (r == 0) ? A0.x : (r == 1) ? A0.y : (r == 2) ? A0.z : A0.w;
            float x1 = (r == 0) ? A1.x : (r == 1) ? A1.y : (r == 2) ? A1.z : A1.w;
            #pragma unroll
            for (int q = 0; q < 8; q++) {
                float4 w = WsV[k * 16 + qb + q];
                acc0[q * 4 + 0] += x0 * w.x; acc0[q * 4 + 1] += x0 * w.y;
                acc0[q * 4 + 2] += x0 * w.z; acc0[q * 4 + 3] += x0 * w.w;
                acc1[q * 4 + 0] += x1 * w.x; acc1[q * 4 + 1] += x1 * w.y;
                acc1[q * 4 + 2] += x1 * w.z; acc1[q * 4 + 3] += x1 * w.w;
            }
        }
    }

    if (v0) {
        float ns = SCALE_SRC ? g_norm[n0] : 1.f;
        float4* o4 = reinterpret_cast<float4*>(g_bufA + (size_t)n0 * DN + half * 32);
        #pragma unroll
        for (int q = 0; q < 8; q++) {
            o4[q] = make_float4(
                fmaxf(acc0[q * 4 + 0] + bs[half * 32 + q * 4 + 0], 0.f) * ns,
                fmaxf(acc0[q * 4 + 1] + bs[half * 32 + q * 4 + 1], 0.f) * ns,
                fmaxf(acc0[q * 4 + 2] + bs[half * 32 + q * 4 + 2], 0.f) * ns,
                fmaxf(acc0[q * 4 + 3] + bs[half * 32 + q * 4 + 3], 0.f) * ns);
        }
    }
    if (v1) {
        float ns = SCALE_SRC ? g_norm[n1] : 1.f;
        float4* o4 = reinterpret_cast<float4*>(g_bufA + (size_t)n1 * DN + half * 32);
        #pragma unroll
        for (int q = 0; q < 8; q++) {
            o4[q] = make_float4(
                fmaxf(acc1[q * 4 + 0] + bs[half * 32 + q * 4 + 0], 0.f) * ns,
                fmaxf(acc1[q * 4 + 1] + bs[half * 32 + q * 4 + 1], 0.f) * ns,
                fmaxf(acc1[q * 4 + 2] + bs[half * 32 + q * 4 + 2], 0.f) * ns,
                fmaxf(acc1[q * 4 + 3] + bs[half * 32 + q * 4 + 3], 0.f) * ns);
        }
    }
}

// ---------------- per-graph mean pool (graph_ids sorted -> run-length accumulate) ----------------
#define POOL_CHUNK 64
__global__ void k_pool(const int* __restrict__ gid, int N) {
    int c = threadIdx.x;                // 64 threads = feature columns
    int n0 = blockIdx.x * POOL_CHUNK;
    if (n0 >= N) return;
    int n1 = min(n0 + POOL_CHUNK, N);

    float acc = 0.f, cnt = 0.f;
    int cur = __ldg(&gid[n0]);
    for (int n = n0; n < n1; n++) {
        int g = __ldg(&gid[n]);
        if (g != cur) {
            atomicAdd(&g_pooled[cur * DN + c], acc);
            if (c == 0) atomicAdd(&g_counts[cur], cnt);
            acc = 0.f; cnt = 0.f; cur = g;
        }
        acc += g_bufA[(size_t)n * DN + c];
        cnt += 1.f;
    }
    atomicAdd(&g_pooled[cur * DN + c], acc);
    if (c == 0) atomicAdd(&g_counts[cur], cnt);
}

// ---------------- classifier ----------------
__global__ void k_classify(const float* __restrict__ Wc, const float* __restrict__ bc,
                           float* __restrict__ out) {
    int g = blockIdx.x;
    int k = threadIdx.x;
    __shared__ float row[DN];
    if (k < DN) row[k] = g_pooled[g * DN + k];
    __syncthreads();
    if (k < 10) {
        float sum = 0.f;
        #pragma unroll
        for (int i = 0; i < DN; i++) sum += row[i] * __ldg(&Wc[i * 10 + k]);
        out[g * 10 + k] = sum / fmaxf(g_counts[g], 1.f) + __ldg(&bc[k]);
    }
}

// ---------------- launch ----------------
extern "C" void kernel_launch(void* const* d_in, const int* in_sizes, int n_in,
                              void* d_out, int out_size) {
    const float* h  = (const float*)d_in[0];
    const float* W1 = (const float*)d_in[1];
    const float* b1 = (const float*)d_in[2];
    const float* W2 = (const float*)d_in[3];
    const float* b2 = (const float*)d_in[4];
    const float* Wc = (const float*)d_in[5];
    const float* bc = (const float*)d_in[6];
    const int* src  = (const int*)d_in[7];
    const int* dst  = (const int*)d_in[8];
    const int* gid  = (const int*)d_in[9];
    float* out = (float*)d_out;

    const int N = in_sizes[9];          // 100000
    const int E = in_sizes[7];          // 1600000
    const int TPB = 256;
    const int G = (N + 1023) / 1024;

    // ---- CSR build (once per launch) ----
    k_zero_init<<<(2 * N + TPB - 1) / TPB, TPB>>>(N);
    k_degree<<<(E + TPB - 1) / TPB, TPB>>>(src, dst, E, N);
    k_scanA<<<G, 1024>>>(N);
    k_scanB<<<1, 128>>>(G);
    k_scanC_norm<<<(N + TPB - 1) / TPB, TPB>>>(N);
    k_fill<<<(E + TPB - 1) / TPB, TPB>>>(src, dst, E);

    // ---- layer 1: gather (h * norm_src) -> bufB; gemm -> bufA (carries *norm_src) ----
    k_gather<true><<<(N * 16 + TPB - 1) / TPB, TPB>>>((const float4*)h, N);
    k_gemm<true><<<(N + 255) / 256, 256>>>(W1, b1, N);

    // ---- layer 2: gather (bufA) -> bufB; gemm -> bufA ----
    k_gather<false><<<(N * 16 + TPB - 1) / TPB, TPB>>>(nullptr, N);
    k_gemm<false><<<(N + 255) / 256, 256>>>(W2, b2, N);

    // ---- pool + classify ----
    k_pool<<<(N + POOL_CHUNK - 1) / POOL_CHUNK, DN>>>(gid, N);
    k_classify<<<NGR, DN>>>(Wc, bc, out);
}

// round 5
// speedup vs baseline: 1.6905x; 1.0025x over previous
#include <cuda_runtime.h>
#include <cuda_fp16.h>
#include <cstdint>

#define NMAX 100000
#define EMAX 1600000
#define DN   64
#define NGR  128

// ---- bit-cast helpers (no intrinsic dependency) ----
__device__ __forceinline__ float2 h2f(unsigned u) {
    __half2 h = *reinterpret_cast<__half2*>(&u);
    return __half22float2(h);
}
__device__ __forceinline__ unsigned f2h(float a, float b) {
    __half2 h = __floats2half2_rn(a, b);
    return *reinterpret_cast<unsigned*>(&h);
}

// ---------------- device scratch (allocation-free) ----------------
__device__ float  g_bufA[NMAX * DN];   // gemm2 output (pool input)
__device__ float  g_bufB[NMAX * DN];   // aggregation target (gather out, gemm in)
__device__ __half g_h16[NMAX * DN];    // fp16 gather source (prescaled features)
__device__ int    g_deg[2 * NMAX];     // [0,N): out-deg(src), [N,2N): in-deg(dst)
__device__ float  g_norm[2 * NMAX];    // [0,N): norm_src, [N,2N): norm_dst
__device__ int    g_off[NMAX];         // CSR row offsets (by dst)
__device__ int    g_blk[128];          // scan block totals
__device__ int    g_cursor[NMAX];      // CSR fill cursors (seeded = g_off)
__device__ int    g_csr[EMAX];         // CSR: src indices grouped by dst
__device__ float  g_pooled[NGR * DN];
__device__ float  g_counts[NGR];

// ---------------- init ----------------
__global__ void k_zero_init(int N) {
    int i = blockIdx.x * blockDim.x + threadIdx.x;
    if (i < 2 * N)      g_deg[i] = 0;
    if (i < NGR * DN)   g_pooled[i] = 0.f;
    if (i < NGR)        g_counts[i] = 0.f;
}

// ---------------- degrees ----------------
__global__ void k_degree(const int* __restrict__ src, const int* __restrict__ dst, int E, int N) {
    int e = blockIdx.x * blockDim.x + threadIdx.x;
    if (e < E) {
        atomicAdd(&g_deg[src[e]], 1);
        atomicAdd(&g_deg[N + dst[e]], 1);
    }
}

// ---------------- exclusive scan of in-degree -> g_off ----------------
__global__ void k_scanA(int N) {
    __shared__ int sh[1024];
    int b = blockIdx.x, t = threadIdx.x, i = b * 1024 + t;
    int v = (i < N) ? g_deg[N + i] : 0;
    sh[t] = v;
    __syncthreads();
    #pragma unroll
    for (int o = 1; o < 1024; o <<= 1) {
        int x = (t >= o) ? sh[t - o] : 0;
        __syncthreads();
        sh[t] += x;
        __syncthreads();
    }
    if (i < N) g_off[i] = sh[t] - v;
    if (t == 1023) g_blk[b] = sh[1023];
}
__global__ void k_scanB(int G) {
    __shared__ int sh[128];
    int t = threadIdx.x;
    int v = (t < G) ? g_blk[t] : 0;
    sh[t] = v;
    __syncthreads();
    #pragma unroll
    for (int o = 1; o < 128; o <<= 1) {
        int x = (t >= o) ? sh[t - o] : 0;
        __syncthreads();
        sh[t] += x;
        __syncthreads();
    }
    if (t < G) g_blk[t] = sh[t] - v;
}
__global__ void k_scanC_norm(int N) {
    int i = blockIdx.x * blockDim.x + threadIdx.x;
    if (i < N) {
        int o = g_off[i] + g_blk[i >> 10];
        g_off[i] = o;
        g_cursor[i] = o;
        g_norm[i]     = rsqrtf((float)max(g_deg[i], 1));
        g_norm[N + i] = rsqrtf((float)max(g_deg[N + i], 1));
    }
}

// ---------------- fill CSR ----------------
__global__ void k_fill(const int* __restrict__ src, const int* __restrict__ dst, int E) {
    int e = blockIdx.x * blockDim.x + threadIdx.x;
    if (e < E) {
        int p = atomicAdd(&g_cursor[dst[e]], 1);
        g_csr[p] = src[e];
    }
}

// ---------------- prep: g_h16[n] = h[n] * norm_src[n] (fp16) ----------------
__global__ void k_prep16(const float4* __restrict__ h, int N) {
    int t = blockIdx.x * blockDim.x + threadIdx.x;
    if (t < N * 16) {
        int n = t >> 4;
        float s = g_norm[n];
        float4 v = h[t];
        uint2 o;
        o.x = f2h(v.x * s, v.y * s);
        o.y = f2h(v.z * s, v.w * s);
        reinterpret_cast<uint2*>(g_h16)[t] = o;
    }
}

// ---------------- gather-sum per dst node (fp16 source, fp32 accum) ----------------
// 8 threads/node, each handles 8 halves (16B). Unrolled x4, dual accumulators.
__global__ void __launch_bounds__(256) k_gather16(int N) {
    int tid = blockIdx.x * blockDim.x + threadIdx.x;
    int node = tid >> 3;
    if (node >= N) return;
    int q = tid & 7;

    int o = g_off[node];
    int d = g_deg[N + node];
    const uint4* X = reinterpret_cast<const uint4*>(g_h16);

    float2 a0[4], a1[4];
    #pragma unroll
    for (int i = 0; i < 4; i++) {
        a0[i] = make_float2(0.f, 0.f);
        a1[i] = make_float2(0.f, 0.f);
    }

    int j = 0;
    for (; j + 4 <= d; j += 4) {
        int s0 = __ldg(&g_csr[o + j]);
        int s1 = __ldg(&g_csr[o + j + 1]);
        int s2 = __ldg(&g_csr[o + j + 2]);
        int s3 = __ldg(&g_csr[o + j + 3]);
        uint4 r0 = __ldg(&X[(size_t)s0 * 8 + q]);
        uint4 r1 = __ldg(&X[(size_t)s1 * 8 + q]);
        uint4 r2 = __ldg(&X[(size_t)s2 * 8 + q]);
        uint4 r3 = __ldg(&X[(size_t)s3 * 8 + q]);
        float2 f;
        f = h2f(r0.x); a0[0].x += f.x; a0[0].y += f.y;
        f = h2f(r0.y); a0[1].x += f.x; a0[1].y += f.y;
        f = h2f(r0.z); a0[2].x += f.x; a0[2].y += f.y;
        f = h2f(r0.w); a0[3].x += f.x; a0[3].y += f.y;
        f = h2f(r1.x); a1[0].x += f.x; a1[0].y += f.y;
        f = h2f(r1.y); a1[1].x += f.x; a1[1].y += f.y;
        f = h2f(r1.z); a1[2].x += f.x; a1[2].y += f.y;
        f = h2f(r1.w); a1[3].x += f.x; a1[3].y += f.y;
        f = h2f(r2.x); a0[0].x += f.x; a0[0].y += f.y;
        f = h2f(r2.y); a0[1].x += f.x; a0[1].y += f.y;
        f = h2f(r2.z); a0[2].x += f.x; a0[2].y += f.y;
        f = h2f(r2.w); a0[3].x += f.x; a0[3].y += f.y;
        f = h2f(r3.x); a1[0].x += f.x; a1[0].y += f.y;
        f = h2f(r3.y); a1[1].x += f.x; a1[1].y += f.y;
        f = h2f(r3.z); a1[2].x += f.x; a1[2].y += f.y;
        f = h2f(r3.w); a1[3].x += f.x; a1[3].y += f.y;
    }
    for (; j < d; j++) {
        int s = __ldg(&g_csr[o + j]);
        uint4 r = __ldg(&X[(size_t)s * 8 + q]);
        float2 f;
        f = h2f(r.x); a0[0].x += f.x; a0[0].y += f.y;
        f = h2f(r.y); a0[1].x += f.x; a0[1].y += f.y;
        f = h2f(r.z); a0[2].x += f.x; a0[2].y += f.y;
        f = h2f(r.w); a0[3].x += f.x; a0[3].y += f.y;
    }

    float nd = g_norm[N + node];
    float4 lo = make_float4((a0[0].x + a1[0].x) * nd, (a0[0].y + a1[0].y) * nd,
                            (a0[1].x + a1[1].x) * nd, (a0[1].y + a1[1].y) * nd);
    float4 hi = make_float4((a0[2].x + a1[2].x) * nd, (a0[2].y + a1[2].y) * nd,
                            (a0[3].x + a1[3].x) * nd, (a0[3].y + a1[3].y) * nd);
    float4* out = reinterpret_cast<float4*>(g_bufB) + (size_t)node * 16 + q * 2;
    out[0] = lo;
    out[1] = hi;
}

// ---------------- GEMM ----------------
// OUT16: write relu(.)*norm_src as fp16 to g_h16 (layer 1). Else fp32 to g_bufA (layer 2).
template<bool OUT16>
__global__ void __launch_bounds__(256) k_gemm(const float* __restrict__ W,
                                              const float* __restrict__ b, int N) {
    __shared__ float Ws[DN * DN];
    __shared__ float bs[DN];
    int tid = threadIdx.x;
    for (int i = tid; i < DN * DN; i += 256) Ws[i] = W[i];
    if (tid < DN) bs[tid] = b[tid];
    __syncthreads();

    int idx = tid >> 1, half = tid & 1;
    int n0 = blockIdx.x * 256 + idx;
    int n1 = n0 + 128;
    bool v0 = n0 < N, v1 = n1 < N;

    const float4* WsV = reinterpret_cast<const float4*>(Ws);
    const float4* a0 = reinterpret_cast<const float4*>(g_bufB + (size_t)n0 * DN);
    const float4* a1 = reinterpret_cast<const float4*>(g_bufB + (size_t)n1 * DN);
    int qb = half * 8;

    float acc0[32], acc1[32];
    #pragma unroll
    for (int j = 0; j < 32; j++) { acc0[j] = 0.f; acc1[j] = 0.f; }

    #pragma unroll
    for (int kk = 0; kk < 16; kk++) {
        float4 A0 = v0 ? a0[kk] : make_float4(0.f, 0.f, 0.f, 0.f);
        float4 A1 = v1 ? a1[kk] : make_float4(0.f, 0.f, 0.f, 0.f);
        #pragma unroll
        for (int r = 0; r < 4; r++) {
            int k = kk * 4 + r;
            float x0 = (r == 0) ? A0.x : (r == 1) ? A0.y : (r == 2) ? A0.z : A0.w;
            float x1 = (r == 0) ? A1.x : (r == 1) ? A1.y : (r == 2) ? A1.z : A1.w;
            #pragma unroll
            for (int q = 0; q < 8; q++) {
                float4 w = WsV[k * 16 + qb + q];
                acc0[q * 4 + 0] += x0 * w.x; acc0[q * 4 + 1] += x0 * w.y;
                acc0[q * 4 + 2] += x0 * w.z; acc0[q * 4 + 3] += x0 * w.w;
                acc1[q * 4 + 0] += x1 * w.x; acc1[q * 4 + 1] += x1 * w.y;
                acc1[q * 4 + 2] += x1 * w.z; acc1[q * 4 + 3] += x1 * w.w;
            }
        }
    }

    #pragma unroll
    for (int which = 0; which < 2; which++) {
        int n = which ? n1 : n0;
        if (which ? !v1 : !v0) continue;
        float* acc = which ? acc1 : acc0;
        if (OUT16) {
            float ns = g_norm[n];
            uint4* dst16 = reinterpret_cast<uint4*>(g_h16 + (size_t)n * DN + half * 32);
            #pragma unroll
            for (int u = 0; u < 4; u++) {
                int j = u * 8;
                float e0 = fmaxf(acc[j + 0] + bs[half * 32 + j + 0], 0.f) * ns;
                float e1 = fmaxf(acc[j + 1] + bs[half * 32 + j + 1], 0.f) * ns;
                float e2 = fmaxf(acc[j + 2] + bs[half * 32 + j + 2], 0.f) * ns;
                float e3 = fmaxf(acc[j + 3] + bs[half * 32 + j + 3], 0.f) * ns;
                float e4 = fmaxf(acc[j + 4] + bs[half * 32 + j + 4], 0.f) * ns;
                float e5 = fmaxf(acc[j + 5] + bs[half * 32 + j + 5], 0.f) * ns;
                float e6 = fmaxf(acc[j + 6] + bs[half * 32 + j + 6], 0.f) * ns;
                float e7 = fmaxf(acc[j + 7] + bs[half * 32 + j + 7], 0.f) * ns;
                uint4 pk;
                pk.x = f2h(e0, e1);
                pk.y = f2h(e2, e3);
                pk.z = f2h(e4, e5);
                pk.w = f2h(e6, e7);
                dst16[u] = pk;
            }
        } else {
            float4* o4 = reinterpret_cast<float4*>(g_bufA + (size_t)n * DN + half * 32);
            #pragma unroll
            for (int qq = 0; qq < 8; qq++) {
                o4[qq] = make_float4(
                    fmaxf(acc[qq * 4 + 0] + bs[half * 32 + qq * 4 + 0], 0.f),
                    fmaxf(acc[qq * 4 + 1] + bs[half * 32 + qq * 4 + 1], 0.f),
                    fmaxf(acc[qq * 4 + 2] + bs[half * 32 + qq * 4 + 2], 0.f),
                    fmaxf(acc[qq * 4 + 3] + bs[half * 32 + qq * 4 + 3], 0.f));
            }
        }
    }
}

// ---------------- per-graph mean pool ----------------
#define POOL_CHUNK 64
__global__ void k_pool(const int* __restrict__ gid, int N) {
    int c = threadIdx.x;
    int n0 = blockIdx.x * POOL_CHUNK;
    if (n0 >= N) return;
    int n1 = min(n0 + POOL_CHUNK, N);

    float acc = 0.f, cnt = 0.f;
    int cur = __ldg(&gid[n0]);
    for (int n = n0; n < n1; n++) {
        int g = __ldg(&gid[n]);
        if (g != cur) {
            atomicAdd(&g_pooled[cur * DN + c], acc);
            if (c == 0) atomicAdd(&g_counts[cur], cnt);
            acc = 0.f; cnt = 0.f; cur = g;
        }
        acc += g_bufA[(size_t)n * DN + c];
        cnt += 1.f;
    }
    atomicAdd(&g_pooled[cur * DN + c], acc);
    if (c == 0) atomicAdd(&g_counts[cur], cnt);
}

// ---------------- classifier ----------------
__global__ void k_classify(const float* __restrict__ Wc, const float* __restrict__ bc,
                           float* __restrict__ out) {
    int g = blockIdx.x;
    int k = threadIdx.x;
    __shared__ float row[DN];
    if (k < DN) row[k] = g_pooled[g * DN + k];
    __syncthreads();
    if (k < 10) {
        float sum = 0.f;
        #pragma unroll
        for (int i = 0; i < DN; i++) sum += row[i] * __ldg(&Wc[i * 10 + k]);
        out[g * 10 + k] = sum / fmaxf(g_counts[g], 1.f) + __ldg(&bc[k]);
    }
}

// ---------------- launch ----------------
extern "C" void kernel_launch(void* const* d_in, const int* in_sizes, int n_in,
                              void* d_out, int out_size) {
    const float* h  = (const float*)d_in[0];
    const float* W1 = (const float*)d_in[1];
    const float* b1 = (const float*)d_in[2];
    const float* W2 = (const float*)d_in[3];
    const float* b2 = (const float*)d_in[4];
    const float* Wc = (const float*)d_in[5];
    const float* bc = (const float*)d_in[6];
    const int* src  = (const int*)d_in[7];
    const int* dst  = (const int*)d_in[8];
    const int* gid  = (const int*)d_in[9];
    float* out = (float*)d_out;

    const int N = in_sizes[9];          // 100000
    const int E = in_sizes[7];          // 1600000
    const int TPB = 256;
    const int G = (N + 1023) / 1024;

    // ---- CSR build ----
    k_zero_init<<<(2 * N + TPB - 1) / TPB, TPB>>>(N);
    k_degree<<<(E + TPB - 1) / TPB, TPB>>>(src, dst, E, N);
    k_scanA<<<G, 1024>>>(N);
    k_scanB<<<1, 128>>>(G);
    k_scanC_norm<<<(N + TPB - 1) / TPB, TPB>>>(N);
    k_fill<<<(E + TPB - 1) / TPB, TPB>>>(src, dst, E);

    // ---- layer 1 ----
    k_prep16<<<(N * 16 + TPB - 1) / TPB, TPB>>>((const float4*)h, N);
    k_gather16<<<(N * 8 + TPB - 1) / TPB, TPB>>>(N);
    k_gemm<true><<<(N + 255) / 256, 256>>>(W1, b1, N);   // -> g_h16 (fp16, *norm_src)

    // ---- layer 2 ----
    k_gather16<<<(N * 8 + TPB - 1) / TPB, TPB>>>(N);
    k_gemm<false><<<(N + 255) / 256, 256>>>(W2, b2, N);  // -> g_bufA (fp32)

    // ---- pool + classify ----
    k_pool<<<(N + POOL_CHUNK - 1) / POOL_CHUNK, DN>>>(gid, N);
    k_classify<<<NGR, DN>>>(Wc, bc, out);
}

// round 6
// speedup vs baseline: 1.7098x; 1.0114x over previous
#include <cuda_runtime.h>
#include <cuda_fp16.h>
#include <cstdint>

#define NMAX 100000
#define EMAX 1600000
#define DN   64
#define NGR  128

// ---- bit-cast helpers ----
__device__ __forceinline__ float2 h2f(unsigned u) {
    __half2 h = *reinterpret_cast<__half2*>(&u);
    return __half22float2(h);
}
__device__ __forceinline__ unsigned f2h(float a, float b) {
    __half2 h = __floats2half2_rn(a, b);
    return *reinterpret_cast<unsigned*>(&h);
}

// ---------------- device scratch (allocation-free) ----------------
__device__ float  g_bufA[NMAX * DN];   // gemm2 output (pool input)
__device__ float  g_bufB[NMAX * DN];   // aggregation target (gather out, gemm in)
__device__ __half g_h16[NMAX * DN];    // fp16 gather source (prescaled features)
__device__ int    g_deg[2 * NMAX];     // [0,N): out-deg(src), [N,2N): in-deg(dst)
__device__ float  g_norm[2 * NMAX];    // [0,N): norm_src, [N,2N): norm_dst
__device__ int    g_off[NMAX];         // CSR row offsets (by dst)
__device__ int    g_blk[128];          // scanA block totals (raw, unscanned)
__device__ int    g_cursor[NMAX];      // CSR fill cursors (seeded = g_off)
__device__ int    g_csr[EMAX];         // CSR: src indices grouped by dst
__device__ float  g_pooled[NGR * DN];
__device__ float  g_counts[NGR];

// ---------------- init ----------------
__global__ void k_zero_init(int N) {
    int i = blockIdx.x * blockDim.x + threadIdx.x;
    if (i < 2 * N)      g_deg[i] = 0;
    if (i < NGR * DN)   g_pooled[i] = 0.f;
    if (i < NGR)        g_counts[i] = 0.f;
}

// ---------------- degrees ----------------
__global__ void k_degree(const int* __restrict__ src, const int* __restrict__ dst, int E, int N) {
    int e = blockIdx.x * blockDim.x + threadIdx.x;
    if (e < E) {
        atomicAdd(&g_deg[src[e]], 1);
        atomicAdd(&g_deg[N + dst[e]], 1);
    }
}

// ---------------- scanA: per-1024-block exclusive scan via warp shuffles ----------------
__global__ void k_scanA(int N) {
    __shared__ int wsum[32];
    int b = blockIdx.x, t = threadIdx.x, i = b * 1024 + t;
    int v = (i < N) ? g_deg[N + i] : 0;
    int x = v;
    #pragma unroll
    for (int o = 1; o < 32; o <<= 1) {
        int y = __shfl_up_sync(0xffffffffu, x, o);
        if ((t & 31) >= o) x += y;
    }
    if ((t & 31) == 31) wsum[t >> 5] = x;
    __syncthreads();
    if (t < 32) {
        int w = wsum[t];
        #pragma unroll
        for (int o = 1; o < 32; o <<= 1) {
            int y = __shfl_up_sync(0xffffffffu, w, o);
            if (t >= o) w += y;
        }
        wsum[t] = w;
    }
    __syncthreads();
    int off = (t >= 32) ? wsum[(t >> 5) - 1] : 0;
    int incl = x + off;
    if (i < N) g_off[i] = incl - v;     // exclusive within block
    if (t == 1023) g_blk[b] = incl;     // block total
}

// ---------------- scanC fused: finalize offsets+cursors+norms AND prep fp16 features ----------------
__global__ void __launch_bounds__(256) k_scanC_prep(const float4* __restrict__ h, int N, int G) {
    __shared__ int sblk[128];
    int t = threadIdx.x;
    int i = blockIdx.x * 256 + t;
    if (t < 128) sblk[t] = (t < 128 && t < G) ? g_blk[t] : 0;
    __syncthreads();
    if (i >= N) return;

    int c = i >> 10;
    int pref = 0;
    for (int b2 = 0; b2 < c; b2++) pref += sblk[b2];   // uniform small loop, smem broadcast
    int o = g_off[i] + pref;
    g_off[i] = o;
    g_cursor[i] = o;
    float ns = rsqrtf((float)max(g_deg[i], 1));
    g_norm[i] = ns;
    g_norm[N + i] = rsqrtf((float)max(g_deg[N + i], 1));

    // convert this node's feature row: g_h16[i] = h[i] * norm_src[i]
    const float4* hr = h + (size_t)i * 16;
    uint2* dr = reinterpret_cast<uint2*>(g_h16) + (size_t)i * 16;
    #pragma unroll
    for (int u = 0; u < 16; u++) {
        float4 v = __ldg(&hr[u]);
        uint2 ou;
        ou.x = f2h(v.x * ns, v.y * ns);
        ou.y = f2h(v.z * ns, v.w * ns);
        dr[u] = ou;
    }
}

// ---------------- fill CSR ----------------
__global__ void k_fill(const int* __restrict__ src, const int* __restrict__ dst, int E) {
    int e = blockIdx.x * blockDim.x + threadIdx.x;
    if (e < E) {
        int p = atomicAdd(&g_cursor[dst[e]], 1);
        g_csr[p] = src[e];
    }
}

// ---------------- gather-sum per dst node (fp16 source, fp32 accum) ----------------
__global__ void __launch_bounds__(256) k_gather16(int N) {
    int tid = blockIdx.x * blockDim.x + threadIdx.x;
    int node = tid >> 3;
    if (node >= N) return;
    int q = tid & 7;

    int o = g_off[node];
    int d = g_deg[N + node];
    const uint4* X = reinterpret_cast<const uint4*>(g_h16);

    float2 a0[4], a1[4];
    #pragma unroll
    for (int i = 0; i < 4; i++) {
        a0[i] = make_float2(0.f, 0.f);
        a1[i] = make_float2(0.f, 0.f);
    }

    int j = 0;
    for (; j + 4 <= d; j += 4) {
        int s0 = __ldg(&g_csr[o + j]);
        int s1 = __ldg(&g_csr[o + j + 1]);
        int s2 = __ldg(&g_csr[o + j + 2]);
        int s3 = __ldg(&g_csr[o + j + 3]);
        uint4 r0 = __ldg(&X[(size_t)s0 * 8 + q]);
        uint4 r1 = __ldg(&X[(size_t)s1 * 8 + q]);
        uint4 r2 = __ldg(&X[(size_t)s2 * 8 + q]);
        uint4 r3 = __ldg(&X[(size_t)s3 * 8 + q]);
        float2 f;
        f = h2f(r0.x); a0[0].x += f.x; a0[0].y += f.y;
        f = h2f(r0.y); a0[1].x += f.x; a0[1].y += f.y;
        f = h2f(r0.z); a0[2].x += f.x; a0[2].y += f.y;
        f = h2f(r0.w); a0[3].x += f.x; a0[3].y += f.y;
        f = h2f(r1.x); a1[0].x += f.x; a1[0].y += f.y;
        f = h2f(r1.y); a1[1].x += f.x; a1[1].y += f.y;
        f = h2f(r1.z); a1[2].x += f.x; a1[2].y += f.y;
        f = h2f(r1.w); a1[3].x += f.x; a1[3].y += f.y;
        f = h2f(r2.x); a0[0].x += f.x; a0[0].y += f.y;
        f = h2f(r2.y); a0[1].x += f.x; a0[1].y += f.y;
        f = h2f(r2.z); a0[2].x += f.x; a0[2].y += f.y;
        f = h2f(r2.w); a0[3].x += f.x; a0[3].y += f.y;
        f = h2f(r3.x); a1[0].x += f.x; a1[0].y += f.y;
        f = h2f(r3.y); a1[1].x += f.x; a1[1].y += f.y;
        f = h2f(r3.z); a1[2].x += f.x; a1[2].y += f.y;
        f = h2f(r3.w); a1[3].x += f.x; a1[3].y += f.y;
    }
    for (; j < d; j++) {
        int s = __ldg(&g_csr[o + j]);
        uint4 r = __ldg(&X[(size_t)s * 8 + q]);
        float2 f;
        f = h2f(r.x); a0[0].x += f.x; a0[0].y += f.y;
        f = h2f(r.y); a0[1].x += f.x; a0[1].y += f.y;
        f = h2f(r.z); a0[2].x += f.x; a0[2].y += f.y;
        f = h2f(r.w); a0[3].x += f.x; a0[3].y += f.y;
    }

    float nd = g_norm[N + node];
    float4 lo = make_float4((a0[0].x + a1[0].x) * nd, (a0[0].y + a1[0].y) * nd,
                            (a0[1].x + a1[1].x) * nd, (a0[1].y + a1[1].y) * nd);
    float4 hi = make_float4((a0[2].x + a1[2].x) * nd, (a0[2].y + a1[2].y) * nd,
                            (a0[3].x + a1[3].x) * nd, (a0[3].y + a1[3].y) * nd);
    float4* out = reinterpret_cast<float4*>(g_bufB) + (size_t)node * 16 + q * 2;
    out[0] = lo;
    out[1] = hi;
}

// ---------------- GEMM ----------------
template<bool OUT16>
__global__ void __launch_bounds__(256) k_gemm(const float* __restrict__ W,
                                              const float* __restrict__ b, int N) {
    __shared__ float Ws[DN * DN];
    __shared__ float bs[DN];
    int tid = threadIdx.x;
    for (int i = tid; i < DN * DN; i += 256) Ws[i] = W[i];
    if (tid < DN) bs[tid] = b[tid];
    __syncthreads();

    int idx = tid >> 1, half = tid & 1;
    int n0 = blockIdx.x * 256 + idx;
    int n1 = n0 + 128;
    bool v0 = n0 < N, v1 = n1 < N;

    const float4* WsV = reinterpret_cast<const float4*>(Ws);
    const float4* a0 = reinterpret_cast<const float4*>(g_bufB + (size_t)n0 * DN);
    const float4* a1 = reinterpret_cast<const float4*>(g_bufB + (size_t)n1 * DN);
    int qb = half * 8;

    float acc0[32], acc1[32];
    #pragma unroll
    for (int j = 0; j < 32; j++) { acc0[j] = 0.f; acc1[j] = 0.f; }

    #pragma unroll
    for (int kk = 0; kk < 16; kk++) {
        float4 A0 = v0 ? a0[kk] : make_float4(0.f, 0.f, 0.f, 0.f);
        float4 A1 = v1 ? a1[kk] : make_float4(0.f, 0.f, 0.f, 0.f);
        #pragma unroll
        for (int r = 0; r < 4; r++) {
            int k = kk * 4 + r;
            float x0 = (r == 0) ? A0.x : (r == 1) ? A0.y : (r == 2) ? A0.z : A0.w;
            float x1 = (r == 0) ? A1.x : (r == 1) ? A1.y : (r == 2) ? A1.z : A1.w;
            #pragma unroll
            for (int q = 0; q < 8; q++) {
                float4 w = WsV[k * 16 + qb + q];
                acc0[q * 4 + 0] += x0 * w.x; acc0[q * 4 + 1] += x0 * w.y;
                acc0[q * 4 + 2] += x0 * w.z; acc0[q * 4 + 3] += x0 * w.w;
                acc1[q * 4 + 0] += x1 * w.x; acc1[q * 4 + 1] += x1 * w.y;
                acc1[q * 4 + 2] += x1 * w.z; acc1[q * 4 + 3] += x1 * w.w;
            }
        }
    }

    #pragma unroll
    for (int which = 0; which < 2; which++) {
        int n = which ? n1 : n0;
        if (which ? !v1 : !v0) continue;
        float* acc = which ? acc1 : acc0;
        if (OUT16) {
            float ns = g_norm[n];
            uint4* dst16 = reinterpret_cast<uint4*>(g_h16 + (size_t)n * DN + half * 32);
            #pragma unroll
            for (int u = 0; u < 4; u++) {
                int j = u * 8;
                float e0 = fmaxf(acc[j + 0] + bs[half * 32 + j + 0], 0.f) * ns;
                float e1 = fmaxf(acc[j + 1] + bs[half * 32 + j + 1], 0.f) * ns;
                float e2 = fmaxf(acc[j + 2] + bs[half * 32 + j + 2], 0.f) * ns;
                float e3 = fmaxf(acc[j + 3] + bs[half * 32 + j + 3], 0.f) * ns;
                float e4 = fmaxf(acc[j + 4] + bs[half * 32 + j + 4], 0.f) * ns;
                float e5 = fmaxf(acc[j + 5] + bs[half * 32 + j + 5], 0.f) * ns;
                float e6 = fmaxf(acc[j + 6] + bs[half * 32 + j + 6], 0.f) * ns;
                float e7 = fmaxf(acc[j + 7] + bs[half * 32 + j + 7], 0.f) * ns;
                uint4 pk;
                pk.x = f2h(e0, e1);
                pk.y = f2h(e2, e3);
                pk.z = f2h(e4, e5);
                pk.w = f2h(e6, e7);
                dst16[u] = pk;
            }
        } else {
            float4* o4 = reinterpret_cast<float4*>(g_bufA + (size_t)n * DN + half * 32);
            #pragma unroll
            for (int qq = 0; qq < 8; qq++) {
                o4[qq] = make_float4(
                    fmaxf(acc[qq * 4 + 0] + bs[half * 32 + qq * 4 + 0], 0.f),
                    fmaxf(acc[qq * 4 + 1] + bs[half * 32 + qq * 4 + 1], 0.f),
                    fmaxf(acc[qq * 4 + 2] + bs[half * 32 + qq * 4 + 2], 0.f),
                    fmaxf(acc[qq * 4 + 3] + bs[half * 32 + qq * 4 + 3], 0.f));
            }
        }
    }
}

// ---------------- per-graph mean pool: 16 node-lanes x 16 float4-columns ----------------
#define PCH 256
__global__ void __launch_bounds__(256) k_pool(const int* __restrict__ gid, int N) {
    int t = threadIdx.x;
    int c4 = t & 15;                    // float4 column (0..15)
    int r  = t >> 4;                    // node lane (0..15)
    int n0 = blockIdx.x * PCH;
    int nEnd = min(n0 + PCH, N);
    const float4* X = reinterpret_cast<const float4*>(g_bufA);

    float4 acc = make_float4(0.f, 0.f, 0.f, 0.f);
    float cnt = 0.f;
    int cur = -1;
    for (int n = n0 + r; n < nEnd; n += 16) {
        int g = __ldg(&gid[n]);
        if (g != cur) {
            if (cur >= 0) {
                float* p = &g_pooled[cur * DN + c4 * 4];
                atomicAdd(p + 0, acc.x); atomicAdd(p + 1, acc.y);
                atomicAdd(p + 2, acc.z); atomicAdd(p + 3, acc.w);
                if (c4 == 0) atomicAdd(&g_counts[cur], cnt);
                acc = make_float4(0.f, 0.f, 0.f, 0.f);
                cnt = 0.f;
            }
            cur = g;
        }
        float4 v = X[(size_t)n * 16 + c4];
        acc.x += v.x; acc.y += v.y; acc.z += v.z; acc.w += v.w;
        cnt += 1.f;
    }
    if (cur >= 0) {
        float* p = &g_pooled[cur * DN + c4 * 4];
        atomicAdd(p + 0, acc.x); atomicAdd(p + 1, acc.y);
        atomicAdd(p + 2, acc.z); atomicAdd(p + 3, acc.w);
        if (c4 == 0) atomicAdd(&g_counts[cur], cnt);
    }
}

// ---------------- classifier ----------------
__global__ void k_classify(const float* __restrict__ Wc, const float* __restrict__ bc,
                           float* __restrict__ out) {
    int g = blockIdx.x;
    int k = threadIdx.x;
    __shared__ float row[DN];
    if (k < DN) row[k] = g_pooled[g * DN + k];
    __syncthreads();
    if (k < 10) {
        float sum = 0.f;
        #pragma unroll
        for (int i = 0; i < DN; i++) sum += row[i] * __ldg(&Wc[i * 10 + k]);
        out[g * 10 + k] = sum / fmaxf(g_counts[g], 1.f) + __ldg(&bc[k]);
    }
}

// ---------------- launch ----------------
extern "C" void kernel_launch(void* const* d_in, const int* in_sizes, int n_in,
                              void* d_out, int out_size) {
    const float* h  = (const float*)d_in[0];
    const float* W1 = (const float*)d_in[1];
    const float* b1 = (const float*)d_in[2];
    const float* W2 = (const float*)d_in[3];
    const float* b2 = (const float*)d_in[4];
    const float* Wc = (const float*)d_in[5];
    const float* bc = (const float*)d_in[6];
    const int* src  = (const int*)d_in[7];
    const int* dst  = (const int*)d_in[8];
    const int* gid  = (const int*)d_in[9];
    float* out = (float*)d_out;

    const int N = in_sizes[9];          // 100000
    const int E = in_sizes[7];          // 1600000
    const int TPB = 256;
    const int G = (N + 1023) / 1024;

    // ---- CSR build (scanB folded into scanC; prep16 fused into scanC) ----
    k_zero_init<<<(2 * N + TPB - 1) / TPB, TPB>>>(N);
    k_degree<<<(E + TPB - 1) / TPB, TPB>>>(src, dst, E, N);
    k_scanA<<<G, 1024>>>(N);
    k_scanC_prep<<<(N + 255) / 256, 256>>>((const float4*)h, N, G);
    k_fill<<<(E + TPB - 1) / TPB, TPB>>>(src, dst, E);

    // ---- layer 1 ----
    k_gather16<<<(N * 8 + TPB - 1) / TPB, TPB>>>(N);
    k_gemm<true><<<(N + 255) / 256, 256>>>(W1, b1, N);   // -> g_h16 (fp16, *norm_src)

    // ---- layer 2 ----
    k_gather16<<<(N * 8 + TPB - 1) / TPB, TPB>>>(N);
    k_gemm<false><<<(N + 255) / 256, 256>>>(W2, b2, N);  // -> g_bufA (fp32)

    // ---- pool + classify ----
    k_pool<<<(N + PCH - 1) / PCH, 256>>>(gid, N);
    k_classify<<<NGR, DN>>>(Wc, bc, out);
}

// round 11
// speedup vs baseline: 1.7603x; 1.0296x over previous
#include <cuda_runtime.h>
#include <cuda_fp16.h>
#include <cstdint>

#define NMAX 100000
#define EMAX 1600000
#define DN   64
#define NGR  128

// ---- bit-cast helpers ----
__device__ __forceinline__ float2 h2f(unsigned u) {
    __half2 h = *reinterpret_cast<__half2*>(&u);
    return __half22float2(h);
}
__device__ __forceinline__ unsigned f2h(float a, float b) {
    __half2 h = __floats2half2_rn(a, b);
    return *reinterpret_cast<unsigned*>(&h);
}

// ---------------- device scratch (allocation-free; referenced ONLY in device code) ----------------
__device__ float  g_bufA[NMAX * DN];   // gemm2 output (pool input)
__device__ float  g_bufB[NMAX * DN];   // aggregation target (gather out, gemm in)
__device__ __half g_h16[NMAX * DN];    // fp16 gather source (prep out / gemm1 out)
__device__ int    g_deg[2 * NMAX];     // [0,N): out-deg(src), [N,2N): in-deg(dst)
__device__ float  g_norm[2 * NMAX];    // [0,N): norm_src, [N,2N): norm_dst
__device__ int    g_off[NMAX];         // CSR row offsets (by dst)
__device__ int    g_blk[128];          // scanA block totals (raw)
__device__ int    g_cursor[NMAX];      // CSR fill cursors (seeded = g_off)
__device__ int    g_csr[EMAX];         // CSR: src indices grouped by dst
__device__ float  g_pooled[NGR * DN];
__device__ float  g_counts[NGR];

// ---------------- init ----------------
__global__ void k_zero_init(int N) {
    int i = blockIdx.x * blockDim.x + threadIdx.x;
    if (i < 2 * N)      g_deg[i] = 0;
    if (i < NGR * DN)   g_pooled[i] = 0.f;
    if (i < NGR)        g_counts[i] = 0.f;
}

// ---------------- degrees ----------------
__global__ void k_degree(const int* __restrict__ src, const int* __restrict__ dst, int E, int N) {
    int e = blockIdx.x * blockDim.x + threadIdx.x;
    if (e < E) {
        atomicAdd(&g_deg[src[e]], 1);
        atomicAdd(&g_deg[N + dst[e]], 1);
    }
}

// ---------------- scanA: per-1024-block exclusive scan via warp shuffles ----------------
__global__ void k_scanA(int N) {
    __shared__ int wsum[32];
    int b = blockIdx.x, t = threadIdx.x, i = b * 1024 + t;
    int v = (i < N) ? g_deg[N + i] : 0;
    int x = v;
    #pragma unroll
    for (int o = 1; o < 32; o <<= 1) {
        int y = __shfl_up_sync(0xffffffffu, x, o);
        if ((t & 31) >= o) x += y;
    }
    if ((t & 31) == 31) wsum[t >> 5] = x;
    __syncthreads();
    if (t < 32) {
        int w = wsum[t];
        #pragma unroll
        for (int o = 1; o < 32; o <<= 1) {
            int y = __shfl_up_sync(0xffffffffu, w, o);
            if (t >= o) w += y;
        }
        wsum[t] = w;
    }
    __syncthreads();
    int off = (t >= 32) ? wsum[(t >> 5) - 1] : 0;
    int incl = x + off;
    if (i < N) g_off[i] = incl - v;
    if (t == 1023) g_blk[b] = incl;
}

// ---------------- scanC (thin): finalize offsets, seed cursors, norms ----------------
__global__ void __launch_bounds__(256) k_scanC(int N, int G) {
    __shared__ int sblk[128];
    int t = threadIdx.x;
    int i = blockIdx.x * 256 + t;
    if (t < 128) sblk[t] = (t < G) ? g_blk[t] : 0;
    __syncthreads();
    if (i >= N) return;
    int c = i >> 10;
    int pref = 0;
    for (int b2 = 0; b2 < c; b2++) pref += sblk[b2];
    int o = g_off[i] + pref;
    g_off[i] = o;
    g_cursor[i] = o;
    g_norm[i]     = rsqrtf((float)max(g_deg[i], 1));
    g_norm[N + i] = rsqrtf((float)max(g_deg[N + i], 1));
}

// ---------------- prep: g_h16[n] = h[n] * norm_src[n] (fp16, streaming, 1.6M threads) ----------------
__global__ void k_prep16(const float4* __restrict__ h, int N) {
    int t = blockIdx.x * blockDim.x + threadIdx.x;
    if (t < N * 16) {
        int n = t >> 4;
        float s = g_norm[n];
        float4 v = h[t];
        uint2 o;
        o.x = f2h(v.x * s, v.y * s);
        o.y = f2h(v.z * s, v.w * s);
        reinterpret_cast<uint2*>(g_h16)[t] = o;
    }
}

// ---------------- fill CSR ----------------
__global__ void k_fill(const int* __restrict__ src, const int* __restrict__ dst, int E) {
    int e = blockIdx.x * blockDim.x + threadIdx.x;
    if (e < E) {
        int p = atomicAdd(&g_cursor[dst[e]], 1);
        g_csr[p] = src[e];
    }
}

// ---------------- gather-sum per dst node (fp16 source g_h16, fp32 accum -> g_bufB) ----------------
// 8 threads/node, each handles 8 halves (16B). Unrolled x4, dual accumulators.
__global__ void __launch_bounds__(256) k_gather16(int N) {
    int tid = blockIdx.x * blockDim.x + threadIdx.x;
    int node = tid >> 3;
    if (node >= N) return;
    int q = tid & 7;

    int o = g_off[node];
    int d = g_deg[N + node];
    const uint4* X = reinterpret_cast<const uint4*>(g_h16);

    float2 a0[4], a1[4];
    #pragma unroll
    for (int i = 0; i < 4; i++) {
        a0[i] = make_float2(0.f, 0.f);
        a1[i] = make_float2(0.f, 0.f);
    }

    int j = 0;
    for (; j + 4 <= d; j += 4) {
        int s0 = __ldg(&g_csr[o + j]);
        int s1 = __ldg(&g_csr[o + j + 1]);
        int s2 = __ldg(&g_csr[o + j + 2]);
        int s3 = __ldg(&g_csr[o + j + 3]);
        uint4 r0 = __ldg(&X[(size_t)s0 * 8 + q]);
        uint4 r1 = __ldg(&X[(size_t)s1 * 8 + q]);
        uint4 r2 = __ldg(&X[(size_t)s2 * 8 + q]);
        uint4 r3 = __ldg(&X[(size_t)s3 * 8 + q]);
        float2 f;
        f = h2f(r0.x); a0[0].x += f.x; a0[0].y += f.y;
        f = h2f(r0.y); a0[1].x += f.x; a0[1].y += f.y;
        f = h2f(r0.z); a0[2].x += f.x; a0[2].y += f.y;
        f = h2f(r0.w); a0[3].x += f.x; a0[3].y += f.y;
        f = h2f(r1.x); a1[0].x += f.x; a1[0].y += f.y;
        f = h2f(r1.y); a1[1].x += f.x; a1[1].y += f.y;
        f = h2f(r1.z); a1[2].x += f.x; a1[2].y += f.y;
        f = h2f(r1.w); a1[3].x += f.x; a1[3].y += f.y;
        f = h2f(r2.x); a0[0].x += f.x; a0[0].y += f.y;
        f = h2f(r2.y); a0[1].x += f.x; a0[1].y += f.y;
        f = h2f(r2.z); a0[2].x += f.x; a0[2].y += f.y;
        f = h2f(r2.w); a0[3].x += f.x; a0[3].y += f.y;
        f = h2f(r3.x); a1[0].x += f.x; a1[0].y += f.y;
        f = h2f(r3.y); a1[1].x += f.x; a1[1].y += f.y;
        f = h2f(r3.z); a1[2].x += f.x; a1[2].y += f.y;
        f = h2f(r3.w); a1[3].x += f.x; a1[3].y += f.y;
    }
    for (; j < d; j++) {
        int s = __ldg(&g_csr[o + j]);
        uint4 r = __ldg(&X[(size_t)s * 8 + q]);
        float2 f;
        f = h2f(r.x); a0[0].x += f.x; a0[0].y += f.y;
        f = h2f(r.y); a0[1].x += f.x; a0[1].y += f.y;
        f = h2f(r.z); a0[2].x += f.x; a0[2].y += f.y;
        f = h2f(r.w); a0[3].x += f.x; a0[3].y += f.y;
    }

    float nd = g_norm[N + node];
    float4 lo = make_float4((a0[0].x + a1[0].x) * nd, (a0[0].y + a1[0].y) * nd,
                            (a0[1].x + a1[1].x) * nd, (a0[1].y + a1[1].y) * nd);
    float4 hi = make_float4((a0[2].x + a1[2].x) * nd, (a0[2].y + a1[2].y) * nd,
                            (a0[3].x + a1[3].x) * nd, (a0[3].y + a1[3].y) * nd);
    float4* out = reinterpret_cast<float4*>(g_bufB) + (size_t)node * 16 + q * 2;
    out[0] = lo;
    out[1] = hi;
}

// ---------------- GEMM (fp32 in g_bufB; OUT16 -> g_h16 fp16 *norm_src, else -> g_bufA fp32) ----
template<bool OUT16>
__global__ void __launch_bounds__(256) k_gemm(const float* __restrict__ W,
                                              const float* __restrict__ b, int N) {
    __shared__ float Ws[DN * DN];
    __shared__ float bs[DN];
    int tid = threadIdx.x;
    for (int i = tid; i < DN * DN; i += 256) Ws[i] = W[i];
    if (tid < DN) bs[tid] = b[tid];
    __syncthreads();

    int idx = tid >> 1, half = tid & 1;
    int n0 = blockIdx.x * 256 + idx;
    int n1 = n0 + 128;
    bool v0 = n0 < N, v1 = n1 < N;

    const float4* WsV = reinterpret_cast<const float4*>(Ws);
    const float4* a0 = reinterpret_cast<const float4*>(g_bufB + (size_t)n0 * DN);
    const float4* a1 = reinterpret_cast<const float4*>(g_bufB + (size_t)n1 * DN);
    int qb = half * 8;

    float acc0[32], acc1[32];
    #pragma unroll
    for (int j = 0; j < 32; j++) { acc0[j] = 0.f; acc1[j] = 0.f; }

    #pragma unroll
    for (int kk = 0; kk < 16; kk++) {
        float4 A0 = v0 ? a0[kk] : make_float4(0.f, 0.f, 0.f, 0.f);
        float4 A1 = v1 ? a1[kk] : make_float4(0.f, 0.f, 0.f, 0.f);
        #pragma unroll
        for (int r = 0; r < 4; r++) {
            int k = kk * 4 + r;
            float x0 = (r == 0) ? A0.x : (r == 1) ? A0.y : (r == 2) ? A0.z : A0.w;
            float x1 = (r == 0) ? A1.x : (r == 1) ? A1.y : (r == 2) ? A1.z : A1.w;
            #pragma unroll
            for (int q = 0; q < 8; q++) {
                float4 w = WsV[k * 16 + qb + q];
                acc0[q * 4 + 0] += x0 * w.x; acc0[q * 4 + 1] += x0 * w.y;
                acc0[q * 4 + 2] += x0 * w.z; acc0[q * 4 + 3] += x0 * w.w;
                acc1[q * 4 + 0] += x1 * w.x; acc1[q * 4 + 1] += x1 * w.y;
                acc1[q * 4 + 2] += x1 * w.z; acc1[q * 4 + 3] += x1 * w.w;
            }
        }
    }

    #pragma unroll
    for (int which = 0; which < 2; which++) {
        int n = which ? n1 : n0;
        if (which ? !v1 : !v0) continue;
        float* acc = which ? acc1 : acc0;
        if (OUT16) {
            float ns = g_norm[n];
            uint4* dst16 = reinterpret_cast<uint4*>(g_h16 + (size_t)n * DN + half * 32);
            #pragma unroll
            for (int u = 0; u < 4; u++) {
                int j = u * 8;
                uint4 pk;
                pk.x = f2h(fmaxf(acc[j + 0] + bs[half * 32 + j + 0], 0.f) * ns,
                           fmaxf(acc[j + 1] + bs[half * 32 + j + 1], 0.f) * ns);
                pk.y = f2h(fmaxf(acc[j + 2] + bs[half * 32 + j + 2], 0.f) * ns,
                           fmaxf(acc[j + 3] + bs[half * 32 + j + 3], 0.f) * ns);
                pk.z = f2h(fmaxf(acc[j + 4] + bs[half * 32 + j + 4], 0.f) * ns,
                           fmaxf(acc[j + 5] + bs[half * 32 + j + 5], 0.f) * ns);
                pk.w = f2h(fmaxf(acc[j + 6] + bs[half * 32 + j + 6], 0.f) * ns,
                           fmaxf(acc[j + 7] + bs[half * 32 + j + 7], 0.f) * ns);
                dst16[u] = pk;
            }
        } else {
            float4* o4 = reinterpret_cast<float4*>(g_bufA + (size_t)n * DN + half * 32);
            #pragma unroll
            for (int qq = 0; qq < 8; qq++) {
                o4[qq] = make_float4(
                    fmaxf(acc[qq * 4 + 0] + bs[half * 32 + qq * 4 + 0], 0.f),
                    fmaxf(acc[qq * 4 + 1] + bs[half * 32 + qq * 4 + 1], 0.f),
                    fmaxf(acc[qq * 4 + 2] + bs[half * 32 + qq * 4 + 2], 0.f),
                    fmaxf(acc[qq * 4 + 3] + bs[half * 32 + qq * 4 + 3], 0.f));
            }
        }
    }
}

// ---------------- per-graph mean pool: 16 node-lanes x 16 float4-columns ----------------
#define PCH 256
__global__ void __launch_bounds__(256) k_pool(const int* __restrict__ gid, int N) {
    int t = threadIdx.x;
    int c4 = t & 15;
    int r  = t >> 4;
    int n0 = blockIdx.x * PCH;
    int nEnd = min(n0 + PCH, N);
    const float4* X = reinterpret_cast<const float4*>(g_bufA);

    float4 acc = make_float4(0.f, 0.f, 0.f, 0.f);
    float cnt = 0.f;
    int cur = -1;
    for (int n = n0 + r; n < nEnd; n += 16) {
        int g = __ldg(&gid[n]);
        if (g != cur) {
            if (cur >= 0) {
                float* p = &g_pooled[cur * DN + c4 * 4];
                atomicAdd(p + 0, acc.x); atomicAdd(p + 1, acc.y);
                atomicAdd(p + 2, acc.z); atomicAdd(p + 3, acc.w);
                if (c4 == 0) atomicAdd(&g_counts[cur], cnt);
                acc = make_float4(0.f, 0.f, 0.f, 0.f);
                cnt = 0.f;
            }
            cur = g;
        }
        float4 v = X[(size_t)n * 16 + c4];
        acc.x += v.x; acc.y += v.y; acc.z += v.z; acc.w += v.w;
        cnt += 1.f;
    }
    if (cur >= 0) {
        float* p = &g_pooled[cur * DN + c4 * 4];
        atomicAdd(p + 0, acc.x); atomicAdd(p + 1, acc.y);
        atomicAdd(p + 2, acc.z); atomicAdd(p + 3, acc.w);
        if (c4 == 0) atomicAdd(&g_counts[cur], cnt);
    }
}

// ---------------- classifier ----------------
__global__ void k_classify(const float* __restrict__ Wc, const float* __restrict__ bc,
                           float* __restrict__ out) {
    int g = blockIdx.x;
    int k = threadIdx.x;
    __shared__ float row[DN];
    if (k < DN) row[k] = g_pooled[g * DN + k];
    __syncthreads();
    if (k < 10) {
        float sum = 0.f;
        #pragma unroll
        for (int i = 0; i < DN; i++) sum += row[i] * __ldg(&Wc[i * 10 + k]);
        out[g * 10 + k] = sum / fmaxf(g_counts[g], 1.f) + __ldg(&bc[k]);
    }
}

// ---------------- launch ----------------
extern "C" void kernel_launch(void* const* d_in, const int* in_sizes, int n_in,
                              void* d_out, int out_size) {
    const float* h  = (const float*)d_in[0];
    const float* W1 = (const float*)d_in[1];
    const float* b1 = (const float*)d_in[2];
    const float* W2 = (const float*)d_in[3];
    const float* b2 = (const float*)d_in[4];
    const float* Wc = (const float*)d_in[5];
    const float* bc = (const float*)d_in[6];
    const int* src  = (const int*)d_in[7];
    const int* dst  = (const int*)d_in[8];
    const int* gid  = (const int*)d_in[9];
    float* out = (float*)d_out;

    const int N = in_sizes[9];          // 100000
    const int E = in_sizes[7];          // 1600000
    const int TPB = 256;
    const int G = (N + 1023) / 1024;

    // ---- CSR build ----
    k_zero_init<<<(2 * N + TPB - 1) / TPB, TPB>>>(N);
    k_degree<<<(E + TPB - 1) / TPB, TPB>>>(src, dst, E, N);
    k_scanA<<<G, 1024>>>(N);
    k_scanC<<<(N + 255) / 256, 256>>>(N, G);
    k_prep16<<<(N * 16 + TPB - 1) / TPB, TPB>>>((const float4*)h, N);
    k_fill<<<(E + TPB - 1) / TPB, TPB>>>(src, dst, E);

    // ---- layer 1: gather(g_h16 = prepped h) -> g_bufB; gemm -> g_h16 (fp16, *norm_src) ----
    k_gather16<<<(N * 8 + TPB - 1) / TPB, TPB>>>(N);
    k_gemm<true><<<(N + 255) / 256, 256>>>(W1, b1, N);

    // ---- layer 2: gather(g_h16 = h1) -> g_bufB; gemm -> g_bufA (fp32) ----
    k_gather16<<<(N * 8 + TPB - 1) / TPB, TPB>>>(N);
    k_gemm<false><<<(N + 255) / 256, 256>>>(W2, b2, N);

    // ---- pool + classify ----
    k_pool<<<(N + PCH - 1) / PCH, 256>>>(gid, N);
    k_classify<<<NGR, DN>>>(Wc, bc, out);
}